// round 2
// baseline (speedup 1.0000x reference)
#include <cuda_runtime.h>

// Problem constants
#define BB 8
#define SS 2048
#define DD 128          // DK == DV == 128
#define MM 16           // query rows per CTA
#define NT 128          // key/value tile width (contraction staging)
#define KSTR 132        // floats per d-row of K/V smem tile (128 + 4 pad)
#define QSTR 36         // floats per d-row of Q/W smem tile (16 rows * float2, stride 18 pairs)

#define NTHREADS 256
#define NTILES (SS / NT)        // 16
#define OUT_W_OFF ((size_t)BB * SS * DD)   // weights follow output in d_out

// Scratch: K transposed to [b][d][s] so score-GEMM staging is coalesced and
// the smem tile is written/read conflict-free.
__device__ float g_kt[(size_t)BB * DD * SS];   // 8 MB static scratch (allowed)

// ---------------------------------------------------------------------------
// Packed f32x2 helpers (Blackwell packed fp32 pipe: 2x FLOP per instruction)
// ---------------------------------------------------------------------------
__device__ __forceinline__ void fma2(unsigned long long& d,
                                     unsigned long long a,
                                     unsigned long long b) {
    asm("fma.rn.f32x2 %0, %1, %2, %0;" : "+l"(d) : "l"(a), "l"(b));
}
__device__ __forceinline__ float2 unpack2(unsigned long long v) {
    float2 r;
    asm("mov.b64 {%0, %1}, %2;" : "=f"(r.x), "=f"(r.y) : "l"(v));
    return r;
}

// ---------------------------------------------------------------------------
// K transpose: g_kt[b][d][s] = K[b][s][d]
// ---------------------------------------------------------------------------
__global__ void transpose_k_kernel(const float* __restrict__ K) {
    __shared__ float tile[32][33];
    int b  = blockIdx.z;
    int s0 = blockIdx.x * 32;
    int d0 = blockIdx.y * 32;
    const float* src = K + (size_t)b * SS * DD;
    float*       dst = g_kt + (size_t)b * DD * SS;
    #pragma unroll
    for (int i = threadIdx.y; i < 32; i += 8)
        tile[i][threadIdx.x] = src[(size_t)(s0 + i) * DD + d0 + threadIdx.x];
    __syncthreads();
    #pragma unroll
    for (int i = threadIdx.y; i < 32; i += 8)
        dst[(size_t)(d0 + i) * SS + s0 + threadIdx.x] = tile[threadIdx.x][i];
}

// ---------------------------------------------------------------------------
// Fused attention: per CTA = 16 query rows x full S.
//   phase 1: scores[16][2048] = Q K^T   (fp32, packed FFMA2, smem-resident)
//   phase 2: row softmax in smem, write normalized weights to gmem
//   phase 3: O[16][128] = W V
// smem (floats):
//   sc : [16][2048]              offset 0      (32768)
//   qt : [128][QSTR] pair-dup    offset 32768  (4608)   (Q in ph1, W-tile in ph3)
//   kt : [128][KSTR]             offset 37376  (16896)  (K^T tile in ph1, V tile in ph3)
// total = 54272 floats = 217088 bytes
// ---------------------------------------------------------------------------
#define SMEM_FLOATS 54272
#define SMEM_BYTES  (SMEM_FLOATS * 4)

__global__ __launch_bounds__(NTHREADS, 1)
void attn_kernel(const float* __restrict__ Q,
                 const float* __restrict__ V,
                 float* __restrict__ out) {
    extern __shared__ float sm[];
    float* sc = sm;            // [16][2048]
    float* qt = sm + 32768;    // [128][QSTR]
    float* kt = sm + 37376;    // [128][KSTR]

    const int t  = threadIdx.x;
    const int tx = t & 31;     // 32 column-thread groups (4 cols each)
    const int wy = t >> 5;     // warp id 0..7 -> 2 rows each
    const int b  = blockIdx.y;
    const int q0 = blockIdx.x * MM;

    const int r0 = wy * 2;     // this thread's two query rows
    const int c0 = tx * 4;     // this thread's four columns

    // ---- stage Q transposed + pair-duplicated: qt[d][2r..2r+1] = (q, q) ----
    {
        const float* Qp = Q + ((size_t)b * SS + q0) * DD;
        #pragma unroll
        for (int i = 0; i < 8; i++) {
            int idx = t + NTHREADS * i;      // 0..2047
            int r = idx >> 7;                // 0..15
            int d = idx & 127;
            float qv = Qp[(size_t)r * DD + d];
            qt[d * QSTR + 2 * r]     = qv;
            qt[d * QSTR + 2 * r + 1] = qv;
        }
    }

    // =========================== phase 1: S = Q K^T =========================
    const float* Kt = g_kt + (size_t)b * DD * SS;
    float4 pre[16];
    #pragma unroll
    for (int i = 0; i < 16; i++) {
        int idx = t + NTHREADS * i;          // 0..4095
        int dd = idx >> 5, c4 = idx & 31;
        pre[i] = *(const float4*)&Kt[(size_t)dd * SS + 4 * c4];
    }

    #pragma unroll 1
    for (int ktile = 0; ktile < NTILES; ktile++) {
        __syncthreads();                     // tile consumed / Q staging done
        #pragma unroll
        for (int i = 0; i < 16; i++) {
            int idx = t + NTHREADS * i;
            int dd = idx >> 5, c4 = idx & 31;
            *(float4*)&kt[dd * KSTR + 4 * c4] = pre[i];
        }
        float4 nxt[16];
        if (ktile + 1 < NTILES) {
            #pragma unroll
            for (int i = 0; i < 16; i++) {
                int idx = t + NTHREADS * i;
                int dd = idx >> 5, c4 = idx & 31;
                nxt[i] = *(const float4*)&Kt[(size_t)dd * SS + (ktile + 1) * NT + 4 * c4];
            }
        }
        __syncthreads();                     // tile visible

        unsigned long long a00 = 0ull, a01 = 0ull, a10 = 0ull, a11 = 0ull;
        #pragma unroll 8
        for (int d = 0; d < DD; d++) {
            // (q_r0,q_r0),(q_r1,q_r1) broadcast; (k_c0,k_c1),(k_c2,k_c3)
            ulonglong2 qq = *(const ulonglong2*)&qt[d * QSTR + 4 * wy];
            ulonglong2 kk = *(const ulonglong2*)&kt[d * KSTR + c0];
            fma2(a00, qq.x, kk.x); fma2(a01, qq.x, kk.y);
            fma2(a10, qq.y, kk.x); fma2(a11, qq.y, kk.y);
        }
        float2 v00 = unpack2(a00), v01 = unpack2(a01);
        float2 v10 = unpack2(a10), v11 = unpack2(a11);
        *(float4*)&sc[(size_t)r0 * SS + ktile * NT + c0] =
            make_float4(v00.x, v00.y, v01.x, v01.y);
        *(float4*)&sc[(size_t)(r0 + 1) * SS + ktile * NT + c0] =
            make_float4(v10.x, v10.y, v11.x, v11.y);

        if (ktile + 1 < NTILES) {
            #pragma unroll
            for (int i = 0; i < 16; i++) pre[i] = nxt[i];
        }
    }

    __syncthreads();

    // ====================== phase 2: row softmax (per warp) =================
    float* wbase = out + OUT_W_OFF;
    #pragma unroll 1
    for (int rr = 0; rr < 2; rr++) {
        int r = r0 + rr;
        float4* row4 = (float4*)(sc + (size_t)r * SS);
        float m = -3.402823466e38f;
        #pragma unroll
        for (int i = 0; i < 16; i++) {
            float4 v = row4[tx + 32 * i];
            m = fmaxf(m, fmaxf(fmaxf(v.x, v.y), fmaxf(v.z, v.w)));
        }
        #pragma unroll
        for (int o = 16; o > 0; o >>= 1)
            m = fmaxf(m, __shfl_xor_sync(0xffffffffu, m, o));

        float l = 0.f;
        #pragma unroll
        for (int i = 0; i < 16; i++) {
            float4 v = row4[tx + 32 * i];
            v.x = __expf(v.x - m); v.y = __expf(v.y - m);
            v.z = __expf(v.z - m); v.w = __expf(v.w - m);
            l += (v.x + v.y) + (v.z + v.w);
            row4[tx + 32 * i] = v;
        }
        #pragma unroll
        for (int o = 16; o > 0; o >>= 1)
            l += __shfl_xor_sync(0xffffffffu, l, o);
        float inv = 1.0f / l;

        float4* wrow = (float4*)(wbase + ((size_t)b * SS + q0 + r) * SS);
        #pragma unroll
        for (int i = 0; i < 16; i++) {
            float4 v = row4[tx + 32 * i];
            v.x *= inv; v.y *= inv; v.z *= inv; v.w *= inv;
            row4[tx + 32 * i] = v;       // keep normalized W for phase 3
            wrow[tx + 32 * i] = v;       // coalesced gmem write
        }
    }

    // =========================== phase 3: O = W V ===========================
    unsigned long long o00 = 0ull, o01 = 0ull, o10 = 0ull, o11 = 0ull;
    const float* Vp = V + (size_t)b * SS * DD;
    #pragma unroll
    for (int i = 0; i < 16; i++) {
        int idx = t + NTHREADS * i;
        int key = idx >> 5, c4 = idx & 31;
        pre[i] = *(const float4*)&Vp[(size_t)key * DD + 4 * c4];
    }

    #pragma unroll 1
    for (int vt = 0; vt < NTILES; vt++) {
        __syncthreads();                     // previous tile consumed (also covers ph2)
        #pragma unroll
        for (int i = 0; i < 16; i++) {
            int idx = t + NTHREADS * i;
            int key = idx >> 5, c4 = idx & 31;
            *(float4*)&kt[key * KSTR + 4 * c4] = pre[i];
        }
        // stage this tile's W slice transposed + pair-duplicated: qt[k][2r]=(w,w)
        #pragma unroll
        for (int i = 0; i < 8; i++) {
            int idx = t + NTHREADS * i;      // 0..2047
            int r = idx >> 7;
            int k = idx & 127;
            float w = sc[(size_t)r * SS + vt * NT + k];
            qt[k * QSTR + 2 * r]     = w;
            qt[k * QSTR + 2 * r + 1] = w;
        }
        float4 nxt[16];
        if (vt + 1 < NTILES) {
            #pragma unroll
            for (int i = 0; i < 16; i++) {
                int idx = t + NTHREADS * i;
                int key = idx >> 5, c4 = idx & 31;
                nxt[i] = *(const float4*)&Vp[((size_t)(vt + 1) * NT + key) * DD + 4 * c4];
            }
        }
        __syncthreads();

        #pragma unroll 8
        for (int k = 0; k < NT; k++) {
            ulonglong2 ww = *(const ulonglong2*)&qt[k * QSTR + 4 * wy];
            ulonglong2 vv = *(const ulonglong2*)&kt[k * KSTR + c0];
            fma2(o00, ww.x, vv.x); fma2(o01, ww.x, vv.y);
            fma2(o10, ww.y, vv.x); fma2(o11, ww.y, vv.y);
        }
        if (vt + 1 < NTILES) {
            #pragma unroll
            for (int i = 0; i < 16; i++) pre[i] = nxt[i];
        }
    }

    // ---- write O ----
    float2 u00 = unpack2(o00), u01 = unpack2(o01);
    float2 u10 = unpack2(o10), u11 = unpack2(o11);
    float* Op = out + ((size_t)b * SS + q0 + r0) * DD + c0;
    *(float4*)Op        = make_float4(u00.x, u00.y, u01.x, u01.y);
    *(float4*)(Op + DD) = make_float4(u10.x, u10.y, u11.x, u11.y);
}

// ---------------------------------------------------------------------------
extern "C" void kernel_launch(void* const* d_in, const int* in_sizes, int n_in,
                              void* d_out, int out_size) {
    const float* Q = (const float*)d_in[0];
    const float* K = (const float*)d_in[1];
    const float* V = (const float*)d_in[2];
    float* out = (float*)d_out;

    cudaFuncSetAttribute(attn_kernel,
                         cudaFuncAttributeMaxDynamicSharedMemorySize, SMEM_BYTES);

    transpose_k_kernel<<<dim3(SS / 32, DD / 32, BB), dim3(32, 8)>>>(K);
    attn_kernel<<<dim3(SS / MM, BB), NTHREADS, SMEM_BYTES>>>(Q, V, out);
}

// round 3
// speedup vs baseline: 1.8413x; 1.8413x over previous
#include <cuda_runtime.h>
#include <cstdint>

#define BB 8
#define SS 2048
#define DD 128
#define MM 16
#define NTHREADS 256
#define OUT_W_OFF ((size_t)BB * SS * DD)

// ---- smem layout (float offsets) ----
#define SCT_OFF 0                 // scT: [2048][16] = 32768 floats (W transposed, XOR-swizzled float4 granules)
#define QT_OFF  32768             // qt:  [128][36]  = 4608 floats (Q pair-duplicated) ; also softmax scratch
#define STG_OFF 37376             // staging: K 2x(4x2064)=16512 ; V 2x(64x132)=16896 (union)
#define KROW 2064
#define VROW 132
#define KBUF (4 * KROW)           // 8256 floats
#define VBUF (64 * VROW)          // 8448 floats
#define SMEM_FLOATS (STG_OFF + 2 * VBUF)   // 54272
#define SMEM_BYTES  (SMEM_FLOATS * 4)      // 217088

__device__ float g_kt[(size_t)BB * DD * SS];   // K transposed [b][d][s]

// ---- packed f32x2 helpers ----
__device__ __forceinline__ void fma2(unsigned long long& d,
                                     unsigned long long a,
                                     unsigned long long b) {
    asm("fma.rn.f32x2 %0, %1, %2, %0;" : "+l"(d) : "l"(a), "l"(b));
}
__device__ __forceinline__ float2 unpack2(unsigned long long v) {
    float2 r;
    asm("mov.b64 {%0, %1}, %2;" : "=f"(r.x), "=f"(r.y) : "l"(v));
    return r;
}
__device__ __forceinline__ unsigned long long packdup(float x) {
    unsigned long long r;
    asm("mov.b64 %0, {%1, %1};" : "=l"(r) : "f"(x));
    return r;
}

// ---- cp.async helpers ----
__device__ __forceinline__ void cpa16(uint32_t dst, const void* src) {
    asm volatile("cp.async.cg.shared.global [%0], [%1], 16;" :: "r"(dst), "l"(src));
}
__device__ __forceinline__ void cpa_commit() {
    asm volatile("cp.async.commit_group;");
}
__device__ __forceinline__ void cpa_wait1() {
    asm volatile("cp.async.wait_group 1;");
}
__device__ __forceinline__ void cpa_wait0() {
    asm volatile("cp.async.wait_group 0;");
}

// ---------------------------------------------------------------------------
__global__ void transpose_k_kernel(const float* __restrict__ K) {
    __shared__ float tile[32][33];
    int b  = blockIdx.z;
    int s0 = blockIdx.x * 32;
    int d0 = blockIdx.y * 32;
    const float* src = K + (size_t)b * SS * DD;
    float*       dst = g_kt + (size_t)b * DD * SS;
    #pragma unroll
    for (int i = threadIdx.y; i < 32; i += 8)
        tile[i][threadIdx.x] = src[(size_t)(s0 + i) * DD + d0 + threadIdx.x];
    __syncthreads();
    #pragma unroll
    for (int i = threadIdx.y; i < 32; i += 8)
        dst[(size_t)(d0 + i) * SS + s0 + threadIdx.x] = tile[threadIdx.x][i];
}

// ---------------------------------------------------------------------------
__global__ __launch_bounds__(NTHREADS, 1)
void attn_kernel(const float* __restrict__ Q,
                 const float* __restrict__ V,
                 float* __restrict__ out) {
    extern __shared__ float sm[];
    float* scT = sm + SCT_OFF;
    float* qt  = sm + QT_OFF;
    float* stg = sm + STG_OFF;

    const int t    = threadIdx.x;
    const int lane = t & 31;
    const int wrp  = t >> 5;
    const int bz   = blockIdx.y;
    const int q0   = blockIdx.x * MM;

    const float* Kt = g_kt + (size_t)bz * DD * SS;
    const float* Qp = Q + ((size_t)bz * SS + q0) * DD;
    const float* Vp = V + (size_t)bz * SS * DD;

    const uint32_t stg_b = (uint32_t)__cvta_generic_to_shared(stg);

    // ---- issue K chunk 0 (4 d-rows x 2048 floats) ----
    {
        #pragma unroll
        for (int i = 0; i < 8; i++) {
            int idx = t + NTHREADS * i;         // 0..2047 float4s
            int dd = idx >> 9, f = idx & 511;
            cpa16(stg_b + (uint32_t)((dd * KROW + 4 * f) * 4),
                  Kt + (size_t)dd * SS + 4 * f);
        }
        cpa_commit();
    }

    // ---- stage Q pair-duplicated: qt[d][2r..2r+1] = (q,q), stride 36 ----
    #pragma unroll
    for (int i = 0; i < 8; i++) {
        int idx = t + NTHREADS * i;             // 0..2047
        int r = idx >> 7, d = idx & 127;
        float qv = Qp[(size_t)r * DD + d];
        qt[d * 36 + 2 * r]     = qv;
        qt[d * 36 + 2 * r + 1] = qv;
    }

    // ================= phase 1: scores (16 rows x 8 cols per thread) =======
    unsigned long long acc[16][4];
    #pragma unroll
    for (int r = 0; r < 16; r++)
        #pragma unroll
        for (int j = 0; j < 4; j++) acc[r][j] = 0ull;

    #pragma unroll 1
    for (int c = 0; c < 32; c++) {
        if (c < 31) {                            // prefetch chunk c+1
            const float* src = Kt + (size_t)(c + 1) * 4 * SS;
            uint32_t dstb = stg_b + (uint32_t)(((c + 1) & 1) * KBUF * 4);
            #pragma unroll
            for (int i = 0; i < 8; i++) {
                int idx = t + NTHREADS * i;
                int dd = idx >> 9, f = idx & 511;
                cpa16(dstb + (uint32_t)((dd * KROW + 4 * f) * 4),
                      src + (size_t)dd * SS + 4 * f);
            }
            cpa_commit();
            cpa_wait1();
        } else {
            cpa_wait0();
        }
        __syncthreads();

        const float* kb = stg + (c & 1) * KBUF;
        #pragma unroll
        for (int d = 0; d < 4; d++) {
            const float* kr = kb + d * KROW + 8 * t;
            ulonglong2 k01 = *(const ulonglong2*)kr;
            ulonglong2 k23 = *(const ulonglong2*)(kr + 4);
            const float* qrow = qt + (c * 4 + d) * 36;
            #pragma unroll
            for (int p = 0; p < 8; p++) {
                ulonglong2 qq = *(const ulonglong2*)(qrow + 4 * p);
                fma2(acc[2*p  ][0], qq.x, k01.x);
                fma2(acc[2*p  ][1], qq.x, k01.y);
                fma2(acc[2*p  ][2], qq.x, k23.x);
                fma2(acc[2*p  ][3], qq.x, k23.y);
                fma2(acc[2*p+1][0], qq.y, k01.x);
                fma2(acc[2*p+1][1], qq.y, k01.y);
                fma2(acc[2*p+1][2], qq.y, k23.x);
                fma2(acc[2*p+1][3], qq.y, k23.y);
            }
        }
        __syncthreads();
    }

    // ---- issue V chunk 0 early (overlaps softmax) ----
    {
        #pragma unroll
        for (int i = 0; i < 8; i++) {
            int idx = t + NTHREADS * i;          // 0..2047 float4s
            int k = idx >> 5, f = idx & 31;
            cpa16(stg_b + (uint32_t)((k * VROW + 4 * f) * 4),
                  Vp + (size_t)k * DD + 4 * f);
        }
        cpa_commit();
    }

    // ================= phase 2: softmax on register scores ==================
    float s[16][8];
    #pragma unroll
    for (int r = 0; r < 16; r++)
        #pragma unroll
        for (int j = 0; j < 4; j++) {
            float2 v = unpack2(acc[r][j]);
            s[r][2*j] = v.x; s[r][2*j+1] = v.y;
        }

    float* red    = qt;          // [16][9] partials (qt dead)
    float* finals = qt + 160;    // [16] row max
    float* invs   = qt + 192;    // [16] 1/sum

    #pragma unroll
    for (int r = 0; r < 16; r++) {
        float m = s[r][0];
        #pragma unroll
        for (int j = 1; j < 8; j++) m = fmaxf(m, s[r][j]);
        #pragma unroll
        for (int o = 16; o > 0; o >>= 1)
            m = fmaxf(m, __shfl_xor_sync(0xffffffffu, m, o));
        if (lane == r) red[r * 9 + wrp] = m;
    }
    __syncthreads();
    if (t < 16) {
        float m = red[t * 9];
        #pragma unroll
        for (int w2 = 1; w2 < 8; w2++) m = fmaxf(m, red[t * 9 + w2]);
        finals[t] = m;
    }
    __syncthreads();
    #pragma unroll
    for (int r = 0; r < 16; r++) {
        float mx = finals[r];
        float l = 0.f;
        #pragma unroll
        for (int j = 0; j < 8; j++) {
            s[r][j] = __expf(s[r][j] - mx);
            l += s[r][j];
        }
        #pragma unroll
        for (int o = 16; o > 0; o >>= 1)
            l += __shfl_xor_sync(0xffffffffu, l, o);
        if (lane == r) red[r * 9 + wrp] = l;
    }
    __syncthreads();
    if (t < 16) {
        float l = 0.f;
        #pragma unroll
        for (int w2 = 0; w2 < 8; w2++) l += red[t * 9 + w2];
        invs[t] = 1.0f / l;
    }
    __syncthreads();

    // scale; write W to gmem; write W transposed+swizzled to scT
    float* wbase = out + OUT_W_OFF + ((size_t)bz * SS + q0) * SS + 8 * t;
    #pragma unroll
    for (int r = 0; r < 16; r++) {
        float inv = invs[r];
        #pragma unroll
        for (int j = 0; j < 8; j++) s[r][j] *= inv;
        *(float4*)(wbase + (size_t)r * SS)     = make_float4(s[r][0], s[r][1], s[r][2], s[r][3]);
        *(float4*)(wbase + (size_t)r * SS + 4) = make_float4(s[r][4], s[r][5], s[r][6], s[r][7]);
    }
    // scT[k][16]: float4 granule g stored at position g ^ ((k>>3)&3)
    {
        int x = t & 3;                       // (k>>3)&3 for k = 8t+j
        #pragma unroll
        for (int j = 0; j < 8; j++) {
            float* base = scT + (8 * t + j) * 16;
            #pragma unroll
            for (int g = 0; g < 4; g++) {
                *(float4*)(base + 4 * (g ^ x)) =
                    make_float4(s[4*g][j], s[4*g+1][j], s[4*g+2][j], s[4*g+3][j]);
            }
        }
    }
    // (visibility of scT ensured by the __syncthreads inside the phase-3 loop)

    // ================= phase 3: O = W V (warps split keys) ==================
    unsigned long long oacc[16][2];
    #pragma unroll
    for (int r = 0; r < 16; r++) { oacc[r][0] = 0ull; oacc[r][1] = 0ull; }

    #pragma unroll 1
    for (int c = 0; c < 32; c++) {
        if (c < 31) {                         // prefetch V chunk c+1
            const float* src = Vp + (size_t)(c + 1) * 64 * DD;
            uint32_t dstb = stg_b + (uint32_t)(((c + 1) & 1) * VBUF * 4);
            #pragma unroll
            for (int i = 0; i < 8; i++) {
                int idx = t + NTHREADS * i;
                int k = idx >> 5, f = idx & 31;
                cpa16(dstb + (uint32_t)((k * VROW + 4 * f) * 4),
                      src + (size_t)k * DD + 4 * f);
            }
            cpa_commit();
            cpa_wait1();
        } else {
            cpa_wait0();
        }
        __syncthreads();

        const float* vb = stg + (c & 1) * VBUF;
        #pragma unroll
        for (int kk = 0; kk < 8; kk++) {
            int kl = 8 * wrp + kk;            // key within chunk (warp-split)
            int kg = c * 64 + kl;             // global key
            const float* wv = scT + kg * 16;
            int x = (kg >> 3) & 3;
            float4 w0 = *(const float4*)(wv + 4 * (0 ^ x));   // rows 0..3
            float4 w1 = *(const float4*)(wv + 4 * (1 ^ x));   // rows 4..7
            float4 w2 = *(const float4*)(wv + 4 * (2 ^ x));   // rows 8..11
            float4 w3 = *(const float4*)(wv + 4 * (3 ^ x));   // rows 12..15
            ulonglong2 vv = *(const ulonglong2*)(vb + kl * VROW + 4 * lane);

            unsigned long long wd;
            wd = packdup(w0.x); fma2(oacc[0][0],  wd, vv.x); fma2(oacc[0][1],  wd, vv.y);
            wd = packdup(w0.y); fma2(oacc[1][0],  wd, vv.x); fma2(oacc[1][1],  wd, vv.y);
            wd = packdup(w0.z); fma2(oacc[2][0],  wd, vv.x); fma2(oacc[2][1],  wd, vv.y);
            wd = packdup(w0.w); fma2(oacc[3][0],  wd, vv.x); fma2(oacc[3][1],  wd, vv.y);
            wd = packdup(w1.x); fma2(oacc[4][0],  wd, vv.x); fma2(oacc[4][1],  wd, vv.y);
            wd = packdup(w1.y); fma2(oacc[5][0],  wd, vv.x); fma2(oacc[5][1],  wd, vv.y);
            wd = packdup(w1.z); fma2(oacc[6][0],  wd, vv.x); fma2(oacc[6][1],  wd, vv.y);
            wd = packdup(w1.w); fma2(oacc[7][0],  wd, vv.x); fma2(oacc[7][1],  wd, vv.y);
            wd = packdup(w2.x); fma2(oacc[8][0],  wd, vv.x); fma2(oacc[8][1],  wd, vv.y);
            wd = packdup(w2.y); fma2(oacc[9][0],  wd, vv.x); fma2(oacc[9][1],  wd, vv.y);
            wd = packdup(w2.z); fma2(oacc[10][0], wd, vv.x); fma2(oacc[10][1], wd, vv.y);
            wd = packdup(w2.w); fma2(oacc[11][0], wd, vv.x); fma2(oacc[11][1], wd, vv.y);
            wd = packdup(w3.x); fma2(oacc[12][0], wd, vv.x); fma2(oacc[12][1], wd, vv.y);
            wd = packdup(w3.y); fma2(oacc[13][0], wd, vv.x); fma2(oacc[13][1], wd, vv.y);
            wd = packdup(w3.z); fma2(oacc[14][0], wd, vv.x); fma2(oacc[14][1], wd, vv.y);
            wd = packdup(w3.w); fma2(oacc[15][0], wd, vv.x); fma2(oacc[15][1], wd, vv.y);
        }
        __syncthreads();
    }

    // ---- reduce 8 warp-partials through smem, write O ----
    float* pool = sm;                          // scT region now dead: [8][16][128]
    #pragma unroll
    for (int r = 0; r < 16; r++) {
        float2 u0 = unpack2(oacc[r][0]);
        float2 u1 = unpack2(oacc[r][1]);
        *(float4*)(pool + wrp * 2048 + r * 128 + 4 * lane) =
            make_float4(u0.x, u0.y, u1.x, u1.y);
    }
    __syncthreads();

    float* Op = out + ((size_t)bz * SS + q0) * DD;
    #pragma unroll
    for (int i = 0; i < 2; i++) {
        int idx = t * 8 + i * 4;
        float4 a = *(float4*)(pool + idx);
        #pragma unroll
        for (int w2 = 1; w2 < 8; w2++) {
            float4 p = *(float4*)(pool + w2 * 2048 + idx);
            a.x += p.x; a.y += p.y; a.z += p.z; a.w += p.w;
        }
        *(float4*)(Op + idx) = a;
    }
}

// ---------------------------------------------------------------------------
extern "C" void kernel_launch(void* const* d_in, const int* in_sizes, int n_in,
                              void* d_out, int out_size) {
    const float* Q = (const float*)d_in[0];
    const float* K = (const float*)d_in[1];
    const float* V = (const float*)d_in[2];
    float* out = (float*)d_out;

    cudaFuncSetAttribute(attn_kernel,
                         cudaFuncAttributeMaxDynamicSharedMemorySize, SMEM_BYTES);

    transpose_k_kernel<<<dim3(SS / 32, DD / 32, BB), dim3(32, 8)>>>(K);
    attn_kernel<<<dim3(SS / MM, BB), NTHREADS, SMEM_BYTES>>>(Q, V, out);
}

// round 6
// speedup vs baseline: 4.0356x; 2.1918x over previous
#include <cuda_runtime.h>
#include <cuda_fp16.h>
#include <cstdint>

#define BB 8
#define SS 2048
#define DD 128
#define NTH 256
#define NCH 32                    // 2048 / 64 keys per chunk
#define OUT_W_OFF ((size_t)BB * SS * DD)

#define RSB 272                   // padded smem row stride (136 halfs) -> conflict-free ldmatrix
#define LO_DELTA 34816            // hi->lo smem delta (uniform for Q/K/V)

#define QH_OFF 0                  // Q hi: 128 x 272 = 34816
#define QL_OFF 34816
#define KH_OFF 69632              // K hi: 2 bufs x (64 x 272 = 17408)
#define KL_OFF 104448
#define VH_OFF 139264
#define VL_OFF 174080
#define L_OFF  208896             // l[128] floats
#define KBUFB  17408
#define SMEM_TOTAL 209920

// fp16 hi/lo split images (written once by prep kernel)
__device__ __half gQh[(size_t)BB * SS * DD];
__device__ __half gQl[(size_t)BB * SS * DD];
__device__ __half gKh[(size_t)BB * SS * DD];
__device__ __half gKl[(size_t)BB * SS * DD];
__device__ __half gVh[(size_t)BB * SS * DD];
__device__ __half gVl[(size_t)BB * SS * DD];

// ============================= helpers =====================================
__device__ __forceinline__ uint32_t smem_u32(const void* p) {
    uint32_t a;
    asm("{ .reg .u64 t; cvta.to.shared.u64 t, %1; cvt.u32.u64 %0, t; }" : "=r"(a) : "l"(p));
    return a;
}
__device__ __forceinline__ void cpa16(uint32_t dst, const void* src) {
    asm volatile("cp.async.cg.shared.global [%0], [%1], 16;" :: "r"(dst), "l"(src));
}
#define CPA_COMMIT() asm volatile("cp.async.commit_group;")
#define CPA_WAIT1()  asm volatile("cp.async.wait_group 1;")
#define CPA_WAIT0()  asm volatile("cp.async.wait_group 0;")

__device__ __forceinline__ void ldsm4(uint32_t& r0, uint32_t& r1, uint32_t& r2, uint32_t& r3,
                                      uint32_t a) {
    asm volatile("ldmatrix.sync.aligned.m8n8.x4.shared.b16 {%0,%1,%2,%3}, [%4];"
                 : "=r"(r0), "=r"(r1), "=r"(r2), "=r"(r3) : "r"(a));
}
__device__ __forceinline__ void ldsm4t(uint32_t& r0, uint32_t& r1, uint32_t& r2, uint32_t& r3,
                                       uint32_t a) {
    asm volatile("ldmatrix.sync.aligned.m8n8.x4.trans.shared.b16 {%0,%1,%2,%3}, [%4];"
                 : "=r"(r0), "=r"(r1), "=r"(r2), "=r"(r3) : "r"(a));
}
__device__ __forceinline__ void mma16816(float* c, uint32_t a0, uint32_t a1, uint32_t a2,
                                         uint32_t a3, uint32_t b0, uint32_t b1) {
    asm volatile("mma.sync.aligned.m16n8k16.row.col.f32.f16.f16.f32 "
                 "{%0,%1,%2,%3}, {%4,%5,%6,%7}, {%8,%9}, {%0,%1,%2,%3};"
                 : "+f"(c[0]), "+f"(c[1]), "+f"(c[2]), "+f"(c[3])
                 : "r"(a0), "r"(a1), "r"(a2), "r"(a3), "r"(b0), "r"(b1));
}
__device__ __forceinline__ void split2(float a, float b, uint32_t& hi, uint32_t& lo) {
    __half ha = __float2half_rn(a), hb = __float2half_rn(b);
    __half la = __float2half_rn(a - __half2float(ha));
    __half lb = __float2half_rn(b - __half2float(hb));
    hi = (uint32_t)__half_as_ushort(ha) | ((uint32_t)__half_as_ushort(hb) << 16);
    lo = (uint32_t)__half_as_ushort(la) | ((uint32_t)__half_as_ushort(lb) << 16);
}

// =========================== prep: fp32 -> hi/lo ===========================
__global__ void prep_split(const float* __restrict__ Q, const float* __restrict__ K,
                           const float* __restrict__ V) {
    size_t i = (size_t)blockIdx.x * NTH + threadIdx.x;
    const float* s;
    __half *dh, *dl;
    if (blockIdx.y == 0)      { s = Q; dh = gQh; dl = gQl; }
    else if (blockIdx.y == 1) { s = K; dh = gKh; dl = gKl; }
    else                      { s = V; dh = gVh; dl = gVl; }
    float x = s[i];
    __half h = __float2half_rn(x);
    dh[i] = h;
    dl[i] = __float2half_rn(x - __half2float(h));
}

// stage one 64-row chunk (hi + lo) into padded smem
__device__ __forceinline__ void stage64(uint32_t dH, uint32_t dL,
                                        const __half* sH, const __half* sL) {
    int t = threadIdx.x;
    #pragma unroll
    for (int i = 0; i < 4; i++) {
        int idx = t + NTH * i;                // 0..1023
        int r = idx >> 4, c = idx & 15;
        uint32_t off = (uint32_t)(r * RSB + c * 16);
        cpa16(dH + off, sH + (size_t)r * DD + c * 8);
        cpa16(dL + off, sL + (size_t)r * DD + c * 8);
    }
}

// S = Q K^T for this warp's 16 rows x 64 keys (3-term fp16 split)
__device__ __forceinline__ void compute_S(float S[8][4], uint32_t qa0, uint32_t kbH,
                                          uint32_t krowoff) {
    #pragma unroll
    for (int r = 0; r < 8; r++) {
        S[r][0] = 0.f; S[r][1] = 0.f; S[r][2] = 0.f; S[r][3] = 0.f;
    }
    #pragma unroll
    for (int kt = 0; kt < 8; kt++) {
        uint32_t qa = qa0 + kt * 32;
        uint32_t qh0, qh1, qh2, qh3, ql0, ql1, ql2, ql3;
        ldsm4(qh0, qh1, qh2, qh3, qa);
        ldsm4(ql0, ql1, ql2, ql3, qa + LO_DELTA);
        #pragma unroll
        for (int ng = 0; ng < 4; ng++) {
            uint32_t ka = kbH + (uint32_t)(ng * 16 * RSB) + krowoff + kt * 32;
            uint32_t kh0, kh1, kh2, kh3, kl0, kl1, kl2, kl3;
            ldsm4(kh0, kh1, kh2, kh3, ka);
            ldsm4(kl0, kl1, kl2, kl3, ka + LO_DELTA);
            mma16816(S[2 * ng], qh0, qh1, qh2, qh3, kh0, kh1);
            mma16816(S[2 * ng], ql0, ql1, ql2, ql3, kh0, kh1);
            mma16816(S[2 * ng], qh0, qh1, qh2, qh3, kl0, kl1);
            mma16816(S[2 * ng + 1], qh0, qh1, qh2, qh3, kh2, kh3);
            mma16816(S[2 * ng + 1], ql0, ql1, ql2, ql3, kh2, kh3);
            mma16816(S[2 * ng + 1], qh0, qh1, qh2, qh3, kl2, kl3);
        }
    }
}

// ============================= main kernel =================================
__global__ __launch_bounds__(NTH, 1)
void attn_mma(float* __restrict__ out) {
    extern __shared__ __align__(1024) unsigned char sm[];
    const uint32_t sb = smem_u32(sm);
    const int t = threadIdx.x, lane = t & 31, w = t >> 5;
    const int b = blockIdx.x >> 4, q0 = (blockIdx.x & 15) * 128;

    const size_t rowbase = (size_t)b * SS;
    const __half* qh = gQh + (rowbase + q0) * DD;
    const __half* ql = gQl + (rowbase + q0) * DD;
    const __half* kh = gKh + rowbase * DD;
    const __half* kl = gKl + rowbase * DD;
    const __half* vh = gVh + rowbase * DD;
    const __half* vl = gVl + rowbase * DD;

    // ldmatrix per-thread address components
    const uint32_t qa0 = sb + QH_OFF +
        (uint32_t)((w * 16 + (lane & 7) + ((lane >> 3) & 1) * 8) * RSB + ((lane >> 4) & 1) * 16);
    const uint32_t krowoff =
        (uint32_t)(((lane & 7) + ((lane >> 4) & 1) * 8) * RSB + ((lane >> 3) & 1) * 16);
    const uint32_t vrowoff =
        (uint32_t)(((lane & 7) + ((lane >> 3) & 1) * 8) * RSB + ((lane >> 4) & 1) * 16);

    // ---- prologue: Q (hi+lo) + K chunk 0 ----
    #pragma unroll
    for (int i = 0; i < 8; i++) {
        int idx = t + NTH * i;                // 0..2047
        int r = idx >> 4, c = idx & 15;
        uint32_t off = (uint32_t)(r * RSB + c * 16);
        cpa16(sb + QH_OFF + off, qh + (size_t)r * DD + c * 8);
        cpa16(sb + QL_OFF + off, ql + (size_t)r * DD + c * 8);
    }
    stage64(sb + KH_OFF, sb + KL_OFF, kh, kl);
    CPA_COMMIT();

    // ============================ pass 1: l ================================
    float lp0 = 0.f, lp1 = 0.f;
    #pragma unroll 1
    for (int j = 0; j < NCH; j++) {
        if (j + 1 < NCH) {
            uint32_t buf = (uint32_t)((j + 1) & 1) * KBUFB;
            stage64(sb + KH_OFF + buf, sb + KL_OFF + buf,
                    kh + (size_t)(j + 1) * 64 * DD, kl + (size_t)(j + 1) * 64 * DD);
            CPA_COMMIT();
            CPA_WAIT1();
        } else {
            CPA_WAIT0();
        }
        __syncthreads();

        float S[8][4];
        compute_S(S, qa0, sb + KH_OFF + (uint32_t)(j & 1) * KBUFB, krowoff);

        #pragma unroll
        for (int nt = 0; nt < 8; nt++) {
            lp0 += __expf(S[nt][0]) + __expf(S[nt][1]);
            lp1 += __expf(S[nt][2]) + __expf(S[nt][3]);
        }
        __syncthreads();
    }

    // reduce l over lane quads, share via smem
    lp0 += __shfl_xor_sync(0xffffffffu, lp0, 1);
    lp0 += __shfl_xor_sync(0xffffffffu, lp0, 2);
    lp1 += __shfl_xor_sync(0xffffffffu, lp1, 1);
    lp1 += __shfl_xor_sync(0xffffffffu, lp1, 2);
    float* lsm = (float*)(sm + L_OFF);
    if ((lane & 3) == 0) {
        lsm[w * 16 + (lane >> 2)] = lp0;
        lsm[w * 16 + (lane >> 2) + 8] = lp1;
    }
    __syncthreads();
    const float linv0 = 1.0f / lsm[w * 16 + (lane >> 2)];
    const float linv1 = 1.0f / lsm[w * 16 + (lane >> 2) + 8];
    __syncthreads();

    // ---- pass-2 prologue: K0 + V0 ----
    stage64(sb + KH_OFF, sb + KL_OFF, kh, kl);
    stage64(sb + VH_OFF, sb + VL_OFF, vh, vl);
    CPA_COMMIT();

    float O[16][4];
    #pragma unroll
    for (int n = 0; n < 16; n++) {
        O[n][0] = 0.f; O[n][1] = 0.f; O[n][2] = 0.f; O[n][3] = 0.f;
    }

    float* wrow0 = out + OUT_W_OFF +
                   (rowbase + q0 + w * 16 + (lane >> 2)) * SS + 2 * (lane & 3);
    float* wrow1 = wrow0 + (size_t)8 * SS;

    // ===================== pass 2: W write + O GEMM ========================
    #pragma unroll 1
    for (int j = 0; j < NCH; j++) {
        if (j + 1 < NCH) {
            uint32_t buf = (uint32_t)((j + 1) & 1) * KBUFB;
            stage64(sb + KH_OFF + buf, sb + KL_OFF + buf,
                    kh + (size_t)(j + 1) * 64 * DD, kl + (size_t)(j + 1) * 64 * DD);
            stage64(sb + VH_OFF + buf, sb + VL_OFF + buf,
                    vh + (size_t)(j + 1) * 64 * DD, vl + (size_t)(j + 1) * 64 * DD);
            CPA_COMMIT();
            CPA_WAIT1();
        } else {
            CPA_WAIT0();
        }
        __syncthreads();

        float S[8][4];
        compute_S(S, qa0, sb + KH_OFF + (uint32_t)(j & 1) * KBUFB, krowoff);

        // normalized weights
        #pragma unroll
        for (int nt = 0; nt < 8; nt++) {
            S[nt][0] = __expf(S[nt][0]) * linv0;
            S[nt][1] = __expf(S[nt][1]) * linv0;
            S[nt][2] = __expf(S[nt][2]) * linv1;
            S[nt][3] = __expf(S[nt][3]) * linv1;
        }

        // W to gmem (32B-sector-aligned float2 stores)
        #pragma unroll
        for (int nt = 0; nt < 8; nt++) {
            *(float2*)(wrow0 + j * 64 + nt * 8) = make_float2(S[nt][0], S[nt][1]);
            *(float2*)(wrow1 + j * 64 + nt * 8) = make_float2(S[nt][2], S[nt][3]);
        }

        // O += W V (3-term split); W C-frags repack directly into A-frags
        const uint32_t vbH = sb + VH_OFF + (uint32_t)(j & 1) * KBUFB;
        #pragma unroll
        for (int kt = 0; kt < 4; kt++) {
            uint32_t wh0, wh1, wh2, wh3, wl0, wl1, wl2, wl3;
            split2(S[2 * kt][0], S[2 * kt][1], wh0, wl0);
            split2(S[2 * kt][2], S[2 * kt][3], wh1, wl1);
            split2(S[2 * kt + 1][0], S[2 * kt + 1][1], wh2, wl2);
            split2(S[2 * kt + 1][2], S[2 * kt + 1][3], wh3, wl3);
            #pragma unroll
            for (int ng = 0; ng < 8; ng++) {
                uint32_t va = vbH + (uint32_t)(kt * 16 * RSB) + vrowoff + ng * 32;
                uint32_t vh0, vh1, vh2, vh3, vl0_, vl1_, vl2_, vl3_;
                ldsm4t(vh0, vh1, vh2, vh3, va);
                ldsm4t(vl0_, vl1_, vl2_, vl3_, va + LO_DELTA);
                mma16816(O[2 * ng], wh0, wh1, wh2, wh3, vh0, vh1);
                mma16816(O[2 * ng], wl0, wl1, wl2, wl3, vh0, vh1);
                mma16816(O[2 * ng], wh0, wh1, wh2, wh3, vl0_, vl1_);
                mma16816(O[2 * ng + 1], wh0, wh1, wh2, wh3, vh2, vh3);
                mma16816(O[2 * ng + 1], wl0, wl1, wl2, wl3, vh2, vh3);
                mma16816(O[2 * ng + 1], wh0, wh1, wh2, wh3, vl2_, vl3_);
            }
        }
        __syncthreads();
    }

    // =========================== O epilogue ================================
    float* orow0 = out + (rowbase + q0 + w * 16 + (lane >> 2)) * DD + 2 * (lane & 3);
    float* orow1 = orow0 + (size_t)8 * DD;
    #pragma unroll
    for (int nt = 0; nt < 16; nt++) {
        *(float2*)(orow0 + nt * 8) = make_float2(O[nt][0], O[nt][1]);
        *(float2*)(orow1 + nt * 8) = make_float2(O[nt][2], O[nt][3]);
    }
}

// ===========================================================================
extern "C" void kernel_launch(void* const* d_in, const int* in_sizes, int n_in,
                              void* d_out, int out_size) {
    const float* Q = (const float*)d_in[0];
    const float* K = (const float*)d_in[1];
    const float* V = (const float*)d_in[2];
    float* out = (float*)d_out;

    cudaFuncSetAttribute(attn_mma, cudaFuncAttributeMaxDynamicSharedMemorySize, SMEM_TOTAL);

    prep_split<<<dim3((BB * SS * DD) / NTH, 3), NTH>>>(Q, K, V);
    attn_mma<<<BB * (SS / 128), NTH, SMEM_TOTAL>>>(out);
}

// round 7
// speedup vs baseline: 4.0726x; 1.0092x over previous
#include <cuda_runtime.h>
#include <cuda_fp16.h>
#include <cstdint>

#define BB 8
#define SS 2048
#define DD 128
#define NTH 256
#define NCH 32                    // 2048 / 64 keys per chunk
#define OUT_W_OFF ((size_t)BB * SS * DD)

#define RSB 272                   // padded smem row stride (136 halfs) -> conflict-free ldmatrix
#define LO_DELTA 34816            // hi->lo smem delta (uniform for Q/K/V)

#define QH_OFF 0                  // Q hi: 128 x 272 = 34816
#define QL_OFF 34816
#define KH_OFF 69632              // K hi: 2 bufs x (64 x 272 = 17408)
#define KL_OFF 104448
#define VH_OFF 139264
#define VL_OFF 174080
#define L_OFF  208896             // winv[128] floats
#define KBUFB  17408
#define SMEM_TOTAL 209920

// fp16 hi/lo split images (written once by prep kernel)
__device__ __half gQh[(size_t)BB * SS * DD];
__device__ __half gQl[(size_t)BB * SS * DD];
__device__ __half gKh[(size_t)BB * SS * DD];
__device__ __half gKl[(size_t)BB * SS * DD];
__device__ __half gVh[(size_t)BB * SS * DD];
__device__ __half gVl[(size_t)BB * SS * DD];

// ============================= helpers =====================================
__device__ __forceinline__ uint32_t smem_u32(const void* p) {
    uint32_t a;
    asm("{ .reg .u64 t; cvta.to.shared.u64 t, %1; cvt.u32.u64 %0, t; }" : "=r"(a) : "l"(p));
    return a;
}
__device__ __forceinline__ void cpa16(uint32_t dst, const void* src) {
    asm volatile("cp.async.cg.shared.global [%0], [%1], 16;" :: "r"(dst), "l"(src));
}
#define CPA_COMMIT() asm volatile("cp.async.commit_group;")
#define CPA_WAIT1()  asm volatile("cp.async.wait_group 1;")
#define CPA_WAIT0()  asm volatile("cp.async.wait_group 0;")

__device__ __forceinline__ void ldsm4(uint32_t& r0, uint32_t& r1, uint32_t& r2, uint32_t& r3,
                                      uint32_t a) {
    asm volatile("ldmatrix.sync.aligned.m8n8.x4.shared.b16 {%0,%1,%2,%3}, [%4];"
                 : "=r"(r0), "=r"(r1), "=r"(r2), "=r"(r3) : "r"(a));
}
__device__ __forceinline__ void ldsm4t(uint32_t& r0, uint32_t& r1, uint32_t& r2, uint32_t& r3,
                                       uint32_t a) {
    asm volatile("ldmatrix.sync.aligned.m8n8.x4.trans.shared.b16 {%0,%1,%2,%3}, [%4];"
                 : "=r"(r0), "=r"(r1), "=r"(r2), "=r"(r3) : "r"(a));
}
__device__ __forceinline__ void mma16816(float* c, uint32_t a0, uint32_t a1, uint32_t a2,
                                         uint32_t a3, uint32_t b0, uint32_t b1) {
    asm volatile("mma.sync.aligned.m16n8k16.row.col.f32.f16.f16.f32 "
                 "{%0,%1,%2,%3}, {%4,%5,%6,%7}, {%8,%9}, {%0,%1,%2,%3};"
                 : "+f"(c[0]), "+f"(c[1]), "+f"(c[2]), "+f"(c[3])
                 : "r"(a0), "r"(a1), "r"(a2), "r"(a3), "r"(b0), "r"(b1));
}
__device__ __forceinline__ void split2(float a, float b, uint32_t& hi, uint32_t& lo) {
    __half ha = __float2half_rn(a), hb = __float2half_rn(b);
    __half la = __float2half_rn(a - __half2float(ha));
    __half lb = __float2half_rn(b - __half2float(hb));
    hi = (uint32_t)__half_as_ushort(ha) | ((uint32_t)__half_as_ushort(hb) << 16);
    lo = (uint32_t)__half_as_ushort(la) | ((uint32_t)__half_as_ushort(lb) << 16);
}

// =========================== prep: fp32 -> hi/lo ===========================
__global__ void prep_split(const float* __restrict__ Q, const float* __restrict__ K,
                           const float* __restrict__ V) {
    size_t i = (size_t)blockIdx.x * NTH + threadIdx.x;
    const float* s;
    __half *dh, *dl;
    if (blockIdx.y == 0)      { s = Q; dh = gQh; dl = gQl; }
    else if (blockIdx.y == 1) { s = K; dh = gKh; dl = gKl; }
    else                      { s = V; dh = gVh; dl = gVl; }
    float x = s[i];
    __half h = __float2half_rn(x);
    dh[i] = h;
    dl[i] = __float2half_rn(x - __half2float(h));
}

// stage one 64-row chunk (hi + lo) into padded smem
__device__ __forceinline__ void stage64(uint32_t dH, uint32_t dL,
                                        const __half* sH, const __half* sL) {
    int t = threadIdx.x;
    #pragma unroll
    for (int i = 0; i < 4; i++) {
        int idx = t + NTH * i;                // 0..1023
        int r = idx >> 4, c = idx & 15;
        uint32_t off = (uint32_t)(r * RSB + c * 16);
        cpa16(dH + off, sH + (size_t)r * DD + c * 8);
        cpa16(dL + off, sL + (size_t)r * DD + c * 8);
    }
}

// S = Q K^T for this warp's 16 rows x 64 keys (3-term fp16 split)
__device__ __forceinline__ void compute_S(float S[8][4], uint32_t qa0, uint32_t kbH,
                                          uint32_t krowoff) {
    #pragma unroll
    for (int r = 0; r < 8; r++) {
        S[r][0] = 0.f; S[r][1] = 0.f; S[r][2] = 0.f; S[r][3] = 0.f;
    }
    #pragma unroll
    for (int kt = 0; kt < 8; kt++) {
        uint32_t qa = qa0 + kt * 32;
        uint32_t qh0, qh1, qh2, qh3, ql0, ql1, ql2, ql3;
        ldsm4(qh0, qh1, qh2, qh3, qa);
        ldsm4(ql0, ql1, ql2, ql3, qa + LO_DELTA);
        #pragma unroll
        for (int ng = 0; ng < 4; ng++) {
            uint32_t ka = kbH + (uint32_t)(ng * 16 * RSB) + krowoff + kt * 32;
            uint32_t kh0, kh1, kh2, kh3, kl0, kl1, kl2, kl3;
            ldsm4(kh0, kh1, kh2, kh3, ka);
            ldsm4(kl0, kl1, kl2, kl3, ka + LO_DELTA);
            mma16816(S[2 * ng], qh0, qh1, qh2, qh3, kh0, kh1);
            mma16816(S[2 * ng], ql0, ql1, ql2, ql3, kh0, kh1);
            mma16816(S[2 * ng], qh0, qh1, qh2, qh3, kl0, kl1);
            mma16816(S[2 * ng + 1], qh0, qh1, qh2, qh3, kh2, kh3);
            mma16816(S[2 * ng + 1], ql0, ql1, ql2, ql3, kh2, kh3);
            mma16816(S[2 * ng + 1], qh0, qh1, qh2, qh3, kl2, kl3);
        }
    }
}

// ============================= main kernel =================================
__global__ __launch_bounds__(NTH, 1)
void attn_mma(float* __restrict__ out) {
    extern __shared__ __align__(1024) unsigned char sm[];
    const uint32_t sb = smem_u32(sm);
    const int t = threadIdx.x, lane = t & 31, w = t >> 5;
    const int b = blockIdx.x >> 4, q0 = (blockIdx.x & 15) * 128;

    const size_t rowbase = (size_t)b * SS;
    const __half* qh = gQh + (rowbase + q0) * DD;
    const __half* ql = gQl + (rowbase + q0) * DD;
    const __half* kh = gKh + rowbase * DD;
    const __half* kl = gKl + rowbase * DD;
    const __half* vh = gVh + rowbase * DD;
    const __half* vl = gVl + rowbase * DD;

    // ldmatrix per-thread address components
    const uint32_t qa0 = sb + QH_OFF +
        (uint32_t)((w * 16 + (lane & 7) + ((lane >> 3) & 1) * 8) * RSB + ((lane >> 4) & 1) * 16);
    const uint32_t krowoff =
        (uint32_t)(((lane & 7) + ((lane >> 4) & 1) * 8) * RSB + ((lane >> 3) & 1) * 16);
    const uint32_t vrowoff =
        (uint32_t)(((lane & 7) + ((lane >> 3) & 1) * 8) * RSB + ((lane >> 4) & 1) * 16);

    // ---- prologue: Q (hi+lo) + K0 + V0 ----
    #pragma unroll
    for (int i = 0; i < 8; i++) {
        int idx = t + NTH * i;                // 0..2047
        int r = idx >> 4, c = idx & 15;
        uint32_t off = (uint32_t)(r * RSB + c * 16);
        cpa16(sb + QH_OFF + off, qh + (size_t)r * DD + c * 8);
        cpa16(sb + QL_OFF + off, ql + (size_t)r * DD + c * 8);
    }
    stage64(sb + KH_OFF, sb + KL_OFF, kh, kl);
    stage64(sb + VH_OFF, sb + VL_OFF, vh, vl);
    CPA_COMMIT();

    float O[16][4];
    #pragma unroll
    for (int n = 0; n < 16; n++) {
        O[n][0] = 0.f; O[n][1] = 0.f; O[n][2] = 0.f; O[n][3] = 0.f;
    }
    float m0 = -3.402823466e38f, m1 = -3.402823466e38f;
    float l0 = 0.f, l1 = 0.f;

    float* wrow0 = out + OUT_W_OFF +
                   (rowbase + q0 + w * 16 + (lane >> 2)) * SS + 2 * (lane & 3);
    float* wrow1 = wrow0 + (size_t)8 * SS;

    // ================== single pass: raw-S store + online O ================
    #pragma unroll 1
    for (int j = 0; j < NCH; j++) {
        if (j + 1 < NCH) {
            uint32_t buf = (uint32_t)((j + 1) & 1) * KBUFB;
            stage64(sb + KH_OFF + buf, sb + KL_OFF + buf,
                    kh + (size_t)(j + 1) * 64 * DD, kl + (size_t)(j + 1) * 64 * DD);
            stage64(sb + VH_OFF + buf, sb + VL_OFF + buf,
                    vh + (size_t)(j + 1) * 64 * DD, vl + (size_t)(j + 1) * 64 * DD);
            CPA_COMMIT();
            CPA_WAIT1();
        } else {
            CPA_WAIT0();
        }
        __syncthreads();

        float S[8][4];
        compute_S(S, qa0, sb + KH_OFF + (uint32_t)(j & 1) * KBUFB, krowoff);

        // raw scores to gmem (fixup sweep normalizes later)
        #pragma unroll
        for (int nt = 0; nt < 8; nt++) {
            *(float2*)(wrow0 + j * 64 + nt * 8) = make_float2(S[nt][0], S[nt][1]);
            *(float2*)(wrow1 + j * 64 + nt * 8) = make_float2(S[nt][2], S[nt][3]);
        }

        // online softmax: row maxima over this chunk
        float cm0 = S[0][0], cm1 = S[0][2];
        #pragma unroll
        for (int nt = 0; nt < 8; nt++) {
            cm0 = fmaxf(cm0, fmaxf(S[nt][0], S[nt][1]));
            cm1 = fmaxf(cm1, fmaxf(S[nt][2], S[nt][3]));
        }
        cm0 = fmaxf(cm0, __shfl_xor_sync(0xffffffffu, cm0, 1));
        cm0 = fmaxf(cm0, __shfl_xor_sync(0xffffffffu, cm0, 2));
        cm1 = fmaxf(cm1, __shfl_xor_sync(0xffffffffu, cm1, 1));
        cm1 = fmaxf(cm1, __shfl_xor_sync(0xffffffffu, cm1, 2));
        float nm0 = fmaxf(m0, cm0), nm1 = fmaxf(m1, cm1);
        float a0 = __expf(m0 - nm0), a1 = __expf(m1 - nm1);
        m0 = nm0; m1 = nm1;
        l0 *= a0; l1 *= a1;

        #pragma unroll
        for (int nt = 0; nt < 8; nt++) {
            S[nt][0] = __expf(S[nt][0] - nm0);
            S[nt][1] = __expf(S[nt][1] - nm0);
            S[nt][2] = __expf(S[nt][2] - nm1);
            S[nt][3] = __expf(S[nt][3] - nm1);
            l0 += S[nt][0] + S[nt][1];
            l1 += S[nt][2] + S[nt][3];
        }
        #pragma unroll
        for (int nt = 0; nt < 16; nt++) {
            O[nt][0] *= a0; O[nt][1] *= a0;
            O[nt][2] *= a1; O[nt][3] *= a1;
        }

        // O += P V (3-term split); P C-frags repack directly into A-frags
        const uint32_t vbH = sb + VH_OFF + (uint32_t)(j & 1) * KBUFB;
        #pragma unroll
        for (int kt = 0; kt < 4; kt++) {
            uint32_t wh0, wh1, wh2, wh3, wl0, wl1, wl2, wl3;
            split2(S[2 * kt][0], S[2 * kt][1], wh0, wl0);
            split2(S[2 * kt][2], S[2 * kt][3], wh1, wl1);
            split2(S[2 * kt + 1][0], S[2 * kt + 1][1], wh2, wl2);
            split2(S[2 * kt + 1][2], S[2 * kt + 1][3], wh3, wl3);
            #pragma unroll
            for (int ng = 0; ng < 8; ng++) {
                uint32_t va = vbH + (uint32_t)(kt * 16 * RSB) + vrowoff + ng * 32;
                uint32_t vh0, vh1, vh2, vh3, vl0_, vl1_, vl2_, vl3_;
                ldsm4t(vh0, vh1, vh2, vh3, va);
                ldsm4t(vl0_, vl1_, vl2_, vl3_, va + LO_DELTA);
                mma16816(O[2 * ng], wh0, wh1, wh2, wh3, vh0, vh1);
                mma16816(O[2 * ng], wl0, wl1, wl2, wl3, vh0, vh1);
                mma16816(O[2 * ng], wh0, wh1, wh2, wh3, vl0_, vl1_);
                mma16816(O[2 * ng + 1], wh0, wh1, wh2, wh3, vh2, vh3);
                mma16816(O[2 * ng + 1], wl0, wl1, wl2, wl3, vh2, vh3);
                mma16816(O[2 * ng + 1], wh0, wh1, wh2, wh3, vl2_, vl3_);
            }
        }
        __syncthreads();
    }

    // =========================== O epilogue ================================
    l0 += __shfl_xor_sync(0xffffffffu, l0, 1);
    l0 += __shfl_xor_sync(0xffffffffu, l0, 2);
    l1 += __shfl_xor_sync(0xffffffffu, l1, 1);
    l1 += __shfl_xor_sync(0xffffffffu, l1, 2);
    const float linv0 = 1.0f / l0, linv1 = 1.0f / l1;

    float* orow0 = out + (rowbase + q0 + w * 16 + (lane >> 2)) * DD + 2 * (lane & 3);
    float* orow1 = orow0 + (size_t)8 * DD;
    #pragma unroll
    for (int nt = 0; nt < 16; nt++) {
        *(float2*)(orow0 + nt * 8) = make_float2(O[nt][0] * linv0, O[nt][1] * linv0);
        *(float2*)(orow1 + nt * 8) = make_float2(O[nt][2] * linv1, O[nt][3] * linv1);
    }

    // publish per-row winv = e^{-m} / l for the fixup sweep
    float* wsm = (float*)(sm + L_OFF);
    if ((lane & 3) == 0) {
        wsm[w * 16 + (lane >> 2)]     = __expf(-m0) * linv0;
        wsm[w * 16 + (lane >> 2) + 8] = __expf(-m1) * linv1;
    }
    __syncthreads();

    // ======================= W fixup sweep (this CTA) ======================
    // W[row][col] = exp(s_raw) * winv[row]; 128 x 2048 fp32 = 65536 float4s
    float4* wbase = (float4*)(out + OUT_W_OFF + (rowbase + q0) * SS);
    #pragma unroll 4
    for (int i = 0; i < 256; i++) {
        int fi = t + NTH * i;                  // 0..65535
        float wv = wsm[fi >> 9];               // 512 float4 per row
        float4 v = wbase[fi];
        v.x = __expf(v.x) * wv;
        v.y = __expf(v.y) * wv;
        v.z = __expf(v.z) * wv;
        v.w = __expf(v.w) * wv;
        wbase[fi] = v;
    }
}

// ===========================================================================
extern "C" void kernel_launch(void* const* d_in, const int* in_sizes, int n_in,
                              void* d_out, int out_size) {
    const float* Q = (const float*)d_in[0];
    const float* K = (const float*)d_in[1];
    const float* V = (const float*)d_in[2];
    float* out = (float*)d_out;

    cudaFuncSetAttribute(attn_mma, cudaFuncAttributeMaxDynamicSharedMemorySize, SMEM_TOTAL);

    prep_split<<<dim3((BB * SS * DD) / NTH, 3), NTH>>>(Q, K, V);
    attn_mma<<<BB * (SS / 128), NTH, SMEM_TOTAL>>>(out);
}

// round 8
// speedup vs baseline: 4.3179x; 1.0603x over previous
#include <cuda_runtime.h>
#include <cuda_fp16.h>
#include <cstdint>

#define BB 8
#define SS 2048
#define DD 128
#define NTH 512
#define NCHG 16                   // chunks of 64 keys per group (each group: 1024 keys)
#define OUT_W_OFF ((size_t)BB * SS * DD)

#define RSB 272                   // padded smem row stride bytes (136 halfs)
#define QLO_D 34816               // Q hi->lo delta
#define KLO_D 17408               // K/V hi->lo delta (64-row chunks)

#define QH_OFF 0                  // Q hi 34816 + lo 34816
#define GK_OFF 69632              // per group: K hi 17408, K lo 17408, V hi 17408, V lo 17408
#define GRP_B  69632              // bytes per group region
#define L_OFF  208896             // m[2][128], l[2][128], winv[128] = 2560 B
#define OMRG   69632              // merge buffer (reuses group-A K/V region) 65536 B
#define SMEM_TOTAL 211456

__device__ __half gQh[(size_t)BB * SS * DD];
__device__ __half gQl[(size_t)BB * SS * DD];
__device__ __half gKh[(size_t)BB * SS * DD];
__device__ __half gKl[(size_t)BB * SS * DD];
__device__ __half gVh[(size_t)BB * SS * DD];
__device__ __half gVl[(size_t)BB * SS * DD];

// ============================= helpers =====================================
__device__ __forceinline__ uint32_t smem_u32(const void* p) {
    uint32_t a;
    asm("{ .reg .u64 t; cvta.to.shared.u64 t, %1; cvt.u32.u64 %0, t; }" : "=r"(a) : "l"(p));
    return a;
}
__device__ __forceinline__ void cpa16(uint32_t dst, const void* src) {
    asm volatile("cp.async.cg.shared.global [%0], [%1], 16;" :: "r"(dst), "l"(src));
}
#define CPA_COMMIT() asm volatile("cp.async.commit_group;")
#define CPA_WAIT0()  asm volatile("cp.async.wait_group 0;")
#define GBAR(id)     asm volatile("bar.sync %0, 256;" :: "r"(id) : "memory")

__device__ __forceinline__ void ldsm4(uint32_t& r0, uint32_t& r1, uint32_t& r2, uint32_t& r3,
                                      uint32_t a) {
    asm volatile("ldmatrix.sync.aligned.m8n8.x4.shared.b16 {%0,%1,%2,%3}, [%4];"
                 : "=r"(r0), "=r"(r1), "=r"(r2), "=r"(r3) : "r"(a));
}
__device__ __forceinline__ void ldsm4t(uint32_t& r0, uint32_t& r1, uint32_t& r2, uint32_t& r3,
                                       uint32_t a) {
    asm volatile("ldmatrix.sync.aligned.m8n8.x4.trans.shared.b16 {%0,%1,%2,%3}, [%4];"
                 : "=r"(r0), "=r"(r1), "=r"(r2), "=r"(r3) : "r"(a));
}
__device__ __forceinline__ void mma16816(float* c, uint32_t a0, uint32_t a1, uint32_t a2,
                                         uint32_t a3, uint32_t b0, uint32_t b1) {
    asm volatile("mma.sync.aligned.m16n8k16.row.col.f32.f16.f16.f32 "
                 "{%0,%1,%2,%3}, {%4,%5,%6,%7}, {%8,%9}, {%0,%1,%2,%3};"
                 : "+f"(c[0]), "+f"(c[1]), "+f"(c[2]), "+f"(c[3])
                 : "r"(a0), "r"(a1), "r"(a2), "r"(a3), "r"(b0), "r"(b1));
}
__device__ __forceinline__ void split2(float a, float b, uint32_t& hi, uint32_t& lo) {
    __half ha = __float2half_rn(a), hb = __float2half_rn(b);
    __half la = __float2half_rn(a - __half2float(ha));
    __half lb = __float2half_rn(b - __half2float(hb));
    hi = (uint32_t)__half_as_ushort(ha) | ((uint32_t)__half_as_ushort(hb) << 16);
    lo = (uint32_t)__half_as_ushort(la) | ((uint32_t)__half_as_ushort(lb) << 16);
}

// =========================== prep: fp32 -> hi/lo ===========================
__global__ void prep_split(const float* __restrict__ Q, const float* __restrict__ K,
                           const float* __restrict__ V) {
    size_t i = (size_t)blockIdx.x * 256 + threadIdx.x;
    const float* s;
    __half *dh, *dl;
    if (blockIdx.y == 0)      { s = Q; dh = gQh; dl = gQl; }
    else if (blockIdx.y == 1) { s = K; dh = gKh; dl = gKl; }
    else                      { s = V; dh = gVh; dl = gVl; }
    float x = s[i];
    __half h = __float2half_rn(x);
    dh[i] = h;
    dl[i] = __float2half_rn(x - __half2float(h));
}

// stage one 64-row hi/lo pair into a group's buffer (256 threads of the group)
__device__ __forceinline__ void stage64g(int tg, uint32_t dH,
                                         const __half* sH, const __half* sL) {
    #pragma unroll
    for (int i = 0; i < 4; i++) {
        int idx = tg + 256 * i;               // 0..1023
        int r = idx >> 4, c = idx & 15;
        uint32_t off = (uint32_t)(r * RSB + c * 16);
        cpa16(dH + off, sH + (size_t)r * DD + c * 8);
        cpa16(dH + KLO_D + off, sL + (size_t)r * DD + c * 8);
    }
}

// S = Q K^T for this warp's 16 rows x 64 keys (3-term fp16 split)
__device__ __forceinline__ void compute_S(float S[8][4], uint32_t qa0, uint32_t kbH,
                                          uint32_t krowoff) {
    #pragma unroll
    for (int r = 0; r < 8; r++) {
        S[r][0] = 0.f; S[r][1] = 0.f; S[r][2] = 0.f; S[r][3] = 0.f;
    }
    #pragma unroll
    for (int kt = 0; kt < 8; kt++) {
        uint32_t qa = qa0 + kt * 32;
        uint32_t qh0, qh1, qh2, qh3, ql0, ql1, ql2, ql3;
        ldsm4(qh0, qh1, qh2, qh3, qa);
        ldsm4(ql0, ql1, ql2, ql3, qa + QLO_D);
        #pragma unroll
        for (int ng = 0; ng < 4; ng++) {
            uint32_t ka = kbH + (uint32_t)(ng * 16 * RSB) + krowoff + kt * 32;
            uint32_t kh0, kh1, kh2, kh3, kl0, kl1, kl2, kl3;
            ldsm4(kh0, kh1, kh2, kh3, ka);
            ldsm4(kl0, kl1, kl2, kl3, ka + KLO_D);
            mma16816(S[2 * ng], qh0, qh1, qh2, qh3, kh0, kh1);
            mma16816(S[2 * ng], ql0, ql1, ql2, ql3, kh0, kh1);
            mma16816(S[2 * ng], qh0, qh1, qh2, qh3, kl0, kl1);
            mma16816(S[2 * ng + 1], qh0, qh1, qh2, qh3, kh2, kh3);
            mma16816(S[2 * ng + 1], ql0, ql1, ql2, ql3, kh2, kh3);
            mma16816(S[2 * ng + 1], qh0, qh1, qh2, qh3, kl2, kl3);
        }
    }
}

// ============================= main kernel =================================
__global__ __launch_bounds__(NTH, 1)
void attn_mma(float* __restrict__ out) {
    extern __shared__ __align__(1024) unsigned char sm[];
    const uint32_t sb = smem_u32(sm);
    const int t = threadIdx.x, lane = t & 31, w = t >> 5;
    const int g = t >> 8, tg = t & 255, gw = w & 7;
    const int b = blockIdx.x >> 4, q0 = (blockIdx.x & 15) * 128;

    const size_t rowbase = (size_t)b * SS;
    const size_t keyoff = (size_t)g * 1024 * DD;        // this group's first key
    const __half* qh = gQh + (rowbase + q0) * DD;
    const __half* ql = gQl + (rowbase + q0) * DD;
    const __half* kh = gKh + rowbase * DD + keyoff;
    const __half* kl = gKl + rowbase * DD + keyoff;
    const __half* vh = gVh + rowbase * DD + keyoff;
    const __half* vl = gVl + rowbase * DD + keyoff;

    const uint32_t kbH = sb + GK_OFF + (uint32_t)g * GRP_B;        // K hi
    const uint32_t vbH = kbH + 2 * KLO_D;                          // V hi
    const int barid = 1 + g;

    const uint32_t qa0 = sb + QH_OFF +
        (uint32_t)((gw * 16 + (lane & 7) + ((lane >> 3) & 1) * 8) * RSB + ((lane >> 4) & 1) * 16);
    const uint32_t krowoff =
        (uint32_t)(((lane & 7) + ((lane >> 4) & 1) * 8) * RSB + ((lane >> 3) & 1) * 16);
    const uint32_t vrowoff =
        (uint32_t)(((lane & 7) + ((lane >> 3) & 1) * 8) * RSB + ((lane >> 4) & 1) * 16);

    // ---- prologue: Q (all threads) + K0/V0 (per group) ----
    #pragma unroll
    for (int i = 0; i < 4; i++) {
        int idx = t + NTH * i;                // 0..2047
        int r = idx >> 4, c = idx & 15;
        uint32_t off = (uint32_t)(r * RSB + c * 16);
        cpa16(sb + QH_OFF + off, qh + (size_t)r * DD + c * 8);
        cpa16(sb + QH_OFF + QLO_D + off, ql + (size_t)r * DD + c * 8);
    }
    stage64g(tg, kbH, kh, kl);
    stage64g(tg, vbH, vh, vl);
    CPA_COMMIT();

    float O[16][4];
    #pragma unroll
    for (int n = 0; n < 16; n++) {
        O[n][0] = 0.f; O[n][1] = 0.f; O[n][2] = 0.f; O[n][3] = 0.f;
    }
    float m0 = -3.402823466e38f, m1 = -3.402823466e38f;
    float l0 = 0.f, l1 = 0.f;

    const int r0 = gw * 16 + (lane >> 2);     // thread's first row (second = r0+8)
    float* wrow0 = out + OUT_W_OFF + (rowbase + q0 + r0) * SS + g * 1024 + 2 * (lane & 3);
    float* wrow1 = wrow0 + (size_t)8 * SS;

    // ===================== group-local chunk loop ==========================
    #pragma unroll 1
    for (int j = 0; j < NCHG; j++) {
        CPA_WAIT0();
        GBAR(barid);                           // K(j), V(j) visible to the group

        float S[8][4];
        compute_S(S, qa0, kbH, krowoff);

        GBAR(barid);                           // group done with K(j)
        if (j + 1 < NCHG)                      // restage K(j+1) under scalar+PV
            stage64g(tg, kbH, kh + (size_t)(j + 1) * 64 * DD,
                     kl + (size_t)(j + 1) * 64 * DD);
        CPA_COMMIT();

        // raw scores to gmem (fixup sweep normalizes later)
        #pragma unroll
        for (int nt = 0; nt < 8; nt++) {
            *(float2*)(wrow0 + j * 64 + nt * 8) = make_float2(S[nt][0], S[nt][1]);
            *(float2*)(wrow1 + j * 64 + nt * 8) = make_float2(S[nt][2], S[nt][3]);
        }

        // online softmax (group-local)
        float cm0 = S[0][0], cm1 = S[0][2];
        #pragma unroll
        for (int nt = 0; nt < 8; nt++) {
            cm0 = fmaxf(cm0, fmaxf(S[nt][0], S[nt][1]));
            cm1 = fmaxf(cm1, fmaxf(S[nt][2], S[nt][3]));
        }
        cm0 = fmaxf(cm0, __shfl_xor_sync(0xffffffffu, cm0, 1));
        cm0 = fmaxf(cm0, __shfl_xor_sync(0xffffffffu, cm0, 2));
        cm1 = fmaxf(cm1, __shfl_xor_sync(0xffffffffu, cm1, 1));
        cm1 = fmaxf(cm1, __shfl_xor_sync(0xffffffffu, cm1, 2));
        float nm0 = fmaxf(m0, cm0), nm1 = fmaxf(m1, cm1);
        float a0 = __expf(m0 - nm0), a1 = __expf(m1 - nm1);
        m0 = nm0; m1 = nm1;
        l0 *= a0; l1 *= a1;
        #pragma unroll
        for (int nt = 0; nt < 8; nt++) {
            S[nt][0] = __expf(S[nt][0] - nm0);
            S[nt][1] = __expf(S[nt][1] - nm0);
            S[nt][2] = __expf(S[nt][2] - nm1);
            S[nt][3] = __expf(S[nt][3] - nm1);
            l0 += S[nt][0] + S[nt][1];
            l1 += S[nt][2] + S[nt][3];
        }
        #pragma unroll
        for (int nt = 0; nt < 16; nt++) {
            O[nt][0] *= a0; O[nt][1] *= a0;
            O[nt][2] *= a1; O[nt][3] *= a1;
        }

        // O += P V (3-term split)
        #pragma unroll
        for (int kt = 0; kt < 4; kt++) {
            uint32_t wh0, wh1, wh2, wh3, wl0, wl1, wl2, wl3;
            split2(S[2 * kt][0], S[2 * kt][1], wh0, wl0);
            split2(S[2 * kt][2], S[2 * kt][3], wh1, wl1);
            split2(S[2 * kt + 1][0], S[2 * kt + 1][1], wh2, wl2);
            split2(S[2 * kt + 1][2], S[2 * kt + 1][3], wh3, wl3);
            #pragma unroll
            for (int ng = 0; ng < 8; ng++) {
                uint32_t va = vbH + (uint32_t)(kt * 16 * RSB) + vrowoff + ng * 32;
                uint32_t x0, x1, x2, x3, y0, y1, y2, y3;
                ldsm4t(x0, x1, x2, x3, va);
                ldsm4t(y0, y1, y2, y3, va + KLO_D);
                mma16816(O[2 * ng], wh0, wh1, wh2, wh3, x0, x1);
                mma16816(O[2 * ng], wl0, wl1, wl2, wl3, x0, x1);
                mma16816(O[2 * ng], wh0, wh1, wh2, wh3, y0, y1);
                mma16816(O[2 * ng + 1], wh0, wh1, wh2, wh3, x2, x3);
                mma16816(O[2 * ng + 1], wl0, wl1, wl2, wl3, x2, x3);
                mma16816(O[2 * ng + 1], wh0, wh1, wh2, wh3, y2, y3);
            }
        }

        GBAR(barid);                           // group done with V(j)
        if (j + 1 < NCHG)
            stage64g(tg, vbH, vh + (size_t)(j + 1) * 64 * DD,
                     vl + (size_t)(j + 1) * 64 * DD);
        CPA_COMMIT();
    }

    // ======================== merge epilogue ===============================
    l0 += __shfl_xor_sync(0xffffffffu, l0, 1);
    l0 += __shfl_xor_sync(0xffffffffu, l0, 2);
    l1 += __shfl_xor_sync(0xffffffffu, l1, 1);
    l1 += __shfl_xor_sync(0xffffffffu, l1, 2);

    float* msm = (float*)(sm + L_OFF);         // [2][128]
    float* lsm = (float*)(sm + L_OFF + 1024);  // [2][128]
    float* wvs = (float*)(sm + L_OFF + 2048);  // winv[128]
    if ((lane & 3) == 0) {
        msm[g * 128 + r0]     = m0;  msm[g * 128 + r0 + 8] = m1;
        lsm[g * 128 + r0]     = l0;  lsm[g * 128 + r0 + 8] = l1;
    }
    __syncthreads();

    float MA0 = msm[r0],       MB0 = msm[128 + r0];
    float MA1 = msm[r0 + 8],   MB1 = msm[128 + r0 + 8];
    float M0 = fmaxf(MA0, MB0), M1 = fmaxf(MA1, MB1);
    float lt0 = __expf(MA0 - M0) * lsm[r0]     + __expf(MB0 - M0) * lsm[128 + r0];
    float lt1 = __expf(MA1 - M1) * lsm[r0 + 8] + __expf(MB1 - M1) * lsm[128 + r0 + 8];
    float sc0 = __expf(m0 - M0) / lt0;         // scale for this thread's own partial
    float sc1 = __expf(m1 - M1) / lt1;
    if (g == 0 && (lane & 3) == 0) {
        wvs[r0]     = __expf(-M0) / lt0;
        wvs[r0 + 8] = __expf(-M1) / lt1;
    }

    float* ob = (float*)(sm + OMRG);           // [128][128]
    if (g == 1) {
        #pragma unroll
        for (int nt = 0; nt < 16; nt++) {
            int col = nt * 8 + (lane & 3) * 2;
            *(float2*)(ob + r0 * 128 + col) =
                make_float2(O[nt][0] * sc0, O[nt][1] * sc0);
            *(float2*)(ob + (r0 + 8) * 128 + col) =
                make_float2(O[nt][2] * sc1, O[nt][3] * sc1);
        }
    }
    __syncthreads();

    if (g == 0) {
        float* orow0 = out + (rowbase + q0 + r0) * DD + 2 * (lane & 3);
        float* orow1 = orow0 + (size_t)8 * DD;
        #pragma unroll
        for (int nt = 0; nt < 16; nt++) {
            int col = nt * 8 + (lane & 3) * 2;
            float2 pb0 = *(float2*)(ob + r0 * 128 + col);
            float2 pb1 = *(float2*)(ob + (r0 + 8) * 128 + col);
            *(float2*)(orow0 + nt * 8) =
                make_float2(O[nt][0] * sc0 + pb0.x, O[nt][1] * sc0 + pb0.y);
            *(float2*)(orow1 + nt * 8) =
                make_float2(O[nt][2] * sc1 + pb1.x, O[nt][3] * sc1 + pb1.y);
        }
    }

    // ======================= W fixup sweep (this CTA) ======================
    float4* wbase = (float4*)(out + OUT_W_OFF + (rowbase + q0) * SS);
    #pragma unroll 4
    for (int i = 0; i < 128; i++) {
        int fi = t + NTH * i;                  // 0..65535
        float wv = wvs[fi >> 9];               // 512 float4 per row
        float4 v = wbase[fi];
        v.x = __expf(v.x) * wv;
        v.y = __expf(v.y) * wv;
        v.z = __expf(v.z) * wv;
        v.w = __expf(v.w) * wv;
        wbase[fi] = v;
    }
}

// ===========================================================================
extern "C" void kernel_launch(void* const* d_in, const int* in_sizes, int n_in,
                              void* d_out, int out_size) {
    const float* Q = (const float*)d_in[0];
    const float* K = (const float*)d_in[1];
    const float* V = (const float*)d_in[2];
    float* out = (float*)d_out;

    cudaFuncSetAttribute(attn_mma, cudaFuncAttributeMaxDynamicSharedMemorySize, SMEM_TOTAL);

    prep_split<<<dim3((BB * SS * DD) / 256, 3), 256>>>(Q, K, V);
    attn_mma<<<BB * (SS / 128), NTH, SMEM_TOTAL>>>(out);
}